// round 6
// baseline (speedup 1.0000x reference)
#include <cuda_runtime.h>
#include <cstdint>

// MaxUnpooling2D: updates [16,64,64,256] f32, mask int32 (flat index over
// (oH,oW,C) per batch), output [16,128,128,256] f32.
//
// Input-centric expansion, 2 float4 quads per thread:
//   each thread owns one (b,h,w) cell and 8 consecutive channels (two c4
//   quads). It front-batches 4x LDG.128 (MLP_p1=4), then writes the 4 output
//   positions of the 2x2 window with 2x STG.128 each (match -> value, else 0).
// Every output element is written exactly once -> no zero-init pass.
// All traffic is touch-once -> streaming hints (__ldcs / __stcs).

#define B_  16
#define H_  64
#define W_  64
#define C_  256
#define OH_ 128
#define OW_ 128
#define C4_ (C_ / 4)                    // 64 float4 quads per pixel
#define C8_ (C_ / 8)                    // 32 thread-owned channel pairs per pixel
#define NTHREADS_TOTAL (B_ * H_ * W_ * C8_)   // 2,097,152

__global__ __launch_bounds__(256)
void maxunpool2d_kernel(const float4* __restrict__ upd4,
                        const int4*  __restrict__ msk4,
                        float4* __restrict__ out4)
{
    const int t = blockIdx.x * blockDim.x + threadIdx.x;

    // Decompose t -> (b, h, w, c8). All dims are powers of two.
    const int c8 = t & (C8_ - 1);
    int r = t >> 5;            // log2(C8_) = 5
    const int w = r & (W_ - 1);
    r >>= 6;                   // log2(W_) = 6
    const int h = r & (H_ - 1);
    const int b = r >> 6;      // log2(H_) = 6

    const int c4 = c8 << 1;    // first float4-quad index of this thread's pair
    // Linear float4 index into the input arrays for quad 0 / quad 1:
    const int iidx = (((b * H_ + h) * W_ + w) * C4_) + c4;

    // Front-batched streaming loads (MLP_p1 = 4).
    const float4 u0 = __ldcs(&upd4[iidx]);
    const float4 u1 = __ldcs(&upd4[iidx + 1]);
    const int4   m0 = __ldcs(&msk4[iidx]);
    const int4   m1 = __ldcs(&msk4[iidx + 1]);

    const int oy = h << 1;
    const int ox = w << 1;
    const int cbase = c4 << 2;               // element channel of u0.x

    // Output float4 index for window position (dy,dx), quad 0:
    //   ((b*OH + oy+dy)*OW + ox+dx)*C4 + c4
    const int obase = ((b * OH_ + oy) * OW_ + ox) * C4_ + c4;

    #pragma unroll
    for (int dy = 0; dy < 2; ++dy) {
        #pragma unroll
        for (int dx = 0; dx < 2; ++dx) {
            // Flat mask target for element (oy+dy, ox+dx, cbase+k):
            const int tb = ((oy + dy) * OW_ + (ox + dx)) * C_ + cbase;
            float4 o0, o1;
            o0.x = (m0.x == tb + 0) ? u0.x : 0.0f;
            o0.y = (m0.y == tb + 1) ? u0.y : 0.0f;
            o0.z = (m0.z == tb + 2) ? u0.z : 0.0f;
            o0.w = (m0.w == tb + 3) ? u0.w : 0.0f;
            o1.x = (m1.x == tb + 4) ? u1.x : 0.0f;
            o1.y = (m1.y == tb + 5) ? u1.y : 0.0f;
            o1.z = (m1.z == tb + 6) ? u1.z : 0.0f;
            o1.w = (m1.w == tb + 7) ? u1.w : 0.0f;
            const int oidx = obase + dy * (OW_ * C4_) + dx * C4_;
            __stcs(&out4[oidx], o0);
            __stcs(&out4[oidx + 1], o1);
        }
    }
}

extern "C" void kernel_launch(void* const* d_in, const int* in_sizes, int n_in,
                              void* d_out, int out_size)
{
    const float4* upd4 = (const float4*)d_in[0];
    const int4*   msk4 = (const int4*)d_in[1];
    float4*       out4 = (float4*)d_out;

    const int threads = 256;
    const int blocks  = NTHREADS_TOTAL / threads;  // 8192, exact coverage
    maxunpool2d_kernel<<<blocks, threads>>>(upd4, msk4, out4);
}

// round 8
// speedup vs baseline: 1.2989x; 1.2989x over previous
#include <cuda_runtime.h>
#include <cstdint>

// MaxUnpooling2D: updates [16,64,64,256] f32, mask int32 (flat index over
// (oH,oW,C) per batch), output [16,128,128,256] f32.
//
// Input-centric expansion, 2 float4 quads per thread, WARP-STRIDED pairing:
//   thread owns quads c8 and c8+32 of its (b,h,w) pixel (C4_=64 quads/pixel,
//   so one warp covers one full pixel). Adjacent threads' addresses for every
//   individual LDG/STG.128 are 16B apart -> dense 512B warp runs (full
//   coalescing), unlike the consecutive-quad variant which produced 32B-strided
//   half-sector accesses. Front-batches 4x LDG.128 (MLP_p1=4).
// Every output element is written exactly once -> no zero-init pass.
// All traffic is touch-once -> streaming hints (__ldcs / __stcs).

#define B_  16
#define H_  64
#define W_  64
#define C_  256
#define OH_ 128
#define OW_ 128
#define C4_ (C_ / 4)                    // 64 float4 quads per pixel
#define C8_ (C_ / 8)                    // 32 quad-pairs per pixel (warp-strided)
#define NTHREADS_TOTAL (B_ * H_ * W_ * C8_)   // 2,097,152

__global__ __launch_bounds__(256)
void maxunpool2d_kernel(const float4* __restrict__ upd4,
                        const int4*  __restrict__ msk4,
                        float4* __restrict__ out4)
{
    const int t = blockIdx.x * blockDim.x + threadIdx.x;

    // Decompose t -> (b, h, w, c8). All dims are powers of two.
    const int c8 = t & (C8_ - 1);    // 0..31, == lane
    int r = t >> 5;                  // log2(C8_) = 5
    const int w = r & (W_ - 1);
    r >>= 6;                         // log2(W_) = 6
    const int h = r & (H_ - 1);
    const int b = r >> 6;            // log2(H_) = 6

    // This thread's two quads: c8 and c8+32 (warp-stride apart).
    const int iidx = (((b * H_ + h) * W_ + w) * C4_) + c8;

    // Front-batched streaming loads (MLP_p1 = 4), each warp-contiguous 512B.
    const float4 u0 = __ldcs(&upd4[iidx]);
    const float4 u1 = __ldcs(&upd4[iidx + 32]);
    const int4   m0 = __ldcs(&msk4[iidx]);
    const int4   m1 = __ldcs(&msk4[iidx + 32]);

    const int oy = h << 1;
    const int ox = w << 1;
    const int cb0 = c8 << 2;          // element channel of u0.x
    const int cb1 = cb0 + 128;        // element channel of u1.x (quad c8+32)

    // Output float4 index for window position (dy,dx), quad 0:
    //   ((b*OH + oy+dy)*OW + ox+dx)*C4 + c8
    const int obase = ((b * OH_ + oy) * OW_ + ox) * C4_ + c8;

    #pragma unroll
    for (int dy = 0; dy < 2; ++dy) {
        #pragma unroll
        for (int dx = 0; dx < 2; ++dx) {
            // Flat mask target base for element (oy+dy, ox+dx, channel):
            const int tp = ((oy + dy) * OW_ + (ox + dx)) * C_;
            const int t0 = tp + cb0;
            const int t1 = tp + cb1;
            float4 o0, o1;
            o0.x = (m0.x == t0 + 0) ? u0.x : 0.0f;
            o0.y = (m0.y == t0 + 1) ? u0.y : 0.0f;
            o0.z = (m0.z == t0 + 2) ? u0.z : 0.0f;
            o0.w = (m0.w == t0 + 3) ? u0.w : 0.0f;
            o1.x = (m1.x == t1 + 0) ? u1.x : 0.0f;
            o1.y = (m1.y == t1 + 1) ? u1.y : 0.0f;
            o1.z = (m1.z == t1 + 2) ? u1.z : 0.0f;
            o1.w = (m1.w == t1 + 3) ? u1.w : 0.0f;
            const int oidx = obase + dy * (OW_ * C4_) + dx * C4_;
            __stcs(&out4[oidx], o0);
            __stcs(&out4[oidx + 32], o1);
        }
    }
}

extern "C" void kernel_launch(void* const* d_in, const int* in_sizes, int n_in,
                              void* d_out, int out_size)
{
    const float4* upd4 = (const float4*)d_in[0];
    const int4*   msk4 = (const int4*)d_in[1];
    float4*       out4 = (float4*)d_out;

    const int threads = 256;
    const int blocks  = NTHREADS_TOTAL / threads;  // 8192, exact coverage
    maxunpool2d_kernel<<<blocks, threads>>>(upd4, msk4, out4);
}